// round 16
// baseline (speedup 1.0000x reference)
#include <cuda_runtime.h>
#include <cuda_fp16.h>
#include <cstdint>

#define NSP   2304
#define CH    512
#define BATCH 8

// ---- unified pure-f16 GEMM params (BK=64, 8 warps, warp tile 32x64) ----
#define BK2    64
#define PAD2   72                      // 64+8 halves; 144B stride, conflict-free
#define MAT2_B (128 * PAD2 * 2)        // 18432 bytes
#define STG2_B (2 * MAT2_B)            // A + B per stage = 36864
#define SMEM4_TOTAL (4 * STG2_B)       // 147456 bytes, 4-stage ring
#define S_NC  ((size_t)NSP * CH)
#define S_NN  ((size_t)NSP * NSP)
#define S_W   ((size_t)CH * CH)

// ---------------- scratch (device globals; no allocations) ------------------
__device__ __half g_tT  [(size_t)BATCH * NSP * CH];
__device__ __half g_iT  [(size_t)BATCH * NSP * CH];
__device__ __half g_w   [(size_t)4 * CH * CH];
__device__ __half g_tfT [(size_t)BATCH * NSP * CH];
__device__ __half g_qT  [(size_t)BATCH * NSP * CH];
__device__ __half g_kT  [(size_t)BATCH * NSP * CH];
__device__ __half g_v   [(size_t)BATCH * CH * NSP];
__device__ float  g_S   [(size_t)BATCH * NSP * NSP];
__device__ __half g_P   [(size_t)BATCH * NSP * NSP];

// ---------------- helpers ----------------------------------------------------
__device__ __forceinline__ uint32_t smem_u32(const void* p) {
    uint32_t a;
    asm("{ .reg .u64 t; cvta.to.shared.u64 t, %1; cvt.u32.u64 %0, t; }" : "=r"(a) : "l"(p));
    return a;
}
__device__ __forceinline__ void cp16(uint32_t saddr, const void* g) {
    asm volatile("cp.async.cg.shared.global [%0], [%1], 16;\n" :: "r"(saddr), "l"(g));
}
__device__ __forceinline__ void cp_commit() { asm volatile("cp.async.commit_group;\n"); }
template<int N> __device__ __forceinline__ void cp_wait() {
    asm volatile("cp.async.wait_group %0;\n" :: "n"(N));
}
__device__ __forceinline__ void ldsm4(unsigned (&r)[4], uint32_t addr) {
    asm volatile("ldmatrix.sync.aligned.m8n8.x4.shared.b16 {%0,%1,%2,%3}, [%4];"
        : "=r"(r[0]), "=r"(r[1]), "=r"(r[2]), "=r"(r[3]) : "r"(addr));
}
__device__ __forceinline__ void mma16816(float (&d)[4], const unsigned (&a)[4],
                                         unsigned b0, unsigned b1) {
    asm volatile(
        "mma.sync.aligned.m16n8k16.row.col.f32.f16.f16.f32 "
        "{%0,%1,%2,%3}, {%4,%5,%6,%7}, {%8,%9}, {%0,%1,%2,%3};\n"
        : "+f"(d[0]), "+f"(d[1]), "+f"(d[2]), "+f"(d[3])
        : "r"(a[0]), "r"(a[1]), "r"(a[2]), "r"(a[3]), "r"(b0), "r"(b1));
}

// ---------------- lane mapping (8 warps, warp tile 32x64) ---------------------
struct LaneMap {
    int lane, warp, wm, wn, grp, qid;
    uint32_t offA, offB;
};
__device__ __forceinline__ LaneMap lane_map(int t) {
    LaneMap L;
    L.lane = t & 31;
    L.warp = t >> 5;
    L.wm   = (L.warp & 3) * 32;
    L.wn   = (L.warp >> 2) * 64;
    L.grp  = L.lane >> 2;
    L.qid  = L.lane & 3;
    L.offA = (uint32_t)(L.wm + (L.lane & 15)) * (PAD2 * 2) + (L.lane >> 4) * 16;
    L.offB = (uint32_t)(L.wn + ((L.lane >> 4) & 1) * 8 + (L.lane & 7)) * (PAD2 * 2)
           + ((L.lane >> 3) & 1) * 16;
    return L;
}

// ============================================================================
// GEMM core: CTA 128x128, 256 threads, BK=64, 4-stage cp.async ring, ONE
// __syncthreads per TWO chunks (128-HMMA trains). Loads issued at window start
// target stages read in window c-2, drained before this window's barrier.
// Per-accumulator k-order identical to R15 (bitwise-same results). nch even.
// ============================================================================
__device__ __forceinline__ void gemm_core(
    const __half* __restrict__ A, const __half* __restrict__ B,
    int K, int m0, int n0, uint32_t sb, int t,
    const LaneMap& L, float (&acc)[2][8][4])
{
    auto load_chunk = [&](int c) {
        const int k0 = c * BK2;
        const uint32_t so = sb + (c & 3) * STG2_B;
#pragma unroll
        for (int i = 0; i < 4; i++) {
            const int idx = t + 256 * i;
            const int kg = idx & 7, r = idx >> 3;
            cp16(so + r * (PAD2 * 2) + kg * 16,
                 &A[(size_t)(m0 + r) * K + k0 + kg * 8]);
        }
#pragma unroll
        for (int i = 0; i < 4; i++) {
            const int idx = t + 256 * i;
            const int kg = idx & 7, r = idx >> 3;
            cp16(so + MAT2_B + r * (PAD2 * 2) + kg * 16,
                 &B[(size_t)(n0 + r) * K + k0 + kg * 8]);
        }
        cp_commit();
    };

    auto compute_chunk = [&](int c) {
        const uint32_t stg = sb + (c & 3) * STG2_B;
#pragma unroll
        for (int ks = 0; ks < 4; ks++) {
            const uint32_t kb2 = ks * 32;
            unsigned a[2][4];
            ldsm4(a[0], stg + L.offA + kb2);
            ldsm4(a[1], stg + L.offA + 16 * (PAD2 * 2) + kb2);
#pragma unroll
            for (int np = 0; np < 4; np++) {
                unsigned b[4];
                ldsm4(b, stg + MAT2_B + L.offB + np * 16 * (PAD2 * 2) + kb2);
                mma16816(acc[0][2 * np],     a[0], b[0], b[1]);
                mma16816(acc[0][2 * np + 1], a[0], b[2], b[3]);
                mma16816(acc[1][2 * np],     a[1], b[0], b[1]);
                mma16816(acc[1][2 * np + 1], a[1], b[2], b[3]);
            }
        }
    };

    const int nch = K / BK2;               // always even here (8 or 36)
    load_chunk(0);
    load_chunk(1);

    for (int c = 0; c < nch; c += 2) {
        cp_wait<0>();                      // chunks c, c+1 resident
        __syncthreads();                   // one barrier per 2 chunks
        if (c + 2 < nch) {                 // prefetch next window; targets
            load_chunk(c + 2);             // stages read in window c-2 (drained)
            load_chunk(c + 3);
        }
        compute_chunk(c);
        compute_chunk(c + 1);
    }
}

__device__ __forceinline__ void zero_acc(float (&acc)[2][8][4]) {
#pragma unroll
    for (int mt = 0; mt < 2; mt++)
#pragma unroll
        for (int nt = 0; nt < 8; nt++)
#pragma unroll
            for (int r = 0; r < 4; r++) acc[mt][nt][r] = 0.f;
}

// ---------------- f16 epilogue with bias (biasN: bias[n] else bias[m]) --------
__device__ __forceinline__ void epi_bias_f16(
    float (&acc)[2][8][4], const LaneMap& L, int m0, int n0, int ldY,
    const float* __restrict__ bias, bool biasN, __half* __restrict__ Y)
{
#pragma unroll
    for (int mt = 0; mt < 2; mt++)
#pragma unroll
        for (int r2 = 0; r2 < 2; r2++) {
            const int m = m0 + L.wm + mt * 16 + L.grp + 8 * r2;
            const float bvr = biasN ? 0.f : bias[m];
#pragma unroll
            for (int nt = 0; nt < 8; nt++) {
                const int n = n0 + L.wn + nt * 8 + L.qid * 2;
                float v0 = acc[mt][nt][r2 * 2 + 0];
                float v1 = acc[mt][nt][r2 * 2 + 1];
                if (biasN) { v0 += bias[n]; v1 += bias[n + 1]; }
                else       { v0 += bvr;     v1 += bvr; }
                *(__half2*)&Y[(size_t)m * ldY + n] =
                    __halves2half2(__float2half_rn(v0), __float2half_rn(v1));
            }
        }
}

// ============================================================================
// Merged tf + Q projection: z = 0..15, op = z>>3 (0: tf, 1: Q). grid (4,18,16)
// ============================================================================
__global__ __launch_bounds__(256, 1)
void proj_tfq(const __half* __restrict__ tT, const __half* __restrict__ iT,
              const __half* __restrict__ w,
              const float* __restrict__ b_tp, const float* __restrict__ b_q,
              __half* __restrict__ tf, __half* __restrict__ q)
{
    extern __shared__ char smem[];
    const uint32_t sb = smem_u32(smem);
    const int t = threadIdx.x;
    const int z = blockIdx.z, op = z >> 3, bz = z & 7;

    const __half* A = (op ? iT : tT) + S_NC * bz;
    const __half* B = w + (size_t)op * S_W;
    const float* bias = op ? b_q : b_tp;
    __half* Y = (op ? q : tf) + S_NC * bz;

    const int n0 = blockIdx.x * 128;
    const int m0 = blockIdx.y * 128;
    const LaneMap L = lane_map(t);

    float acc[2][8][4];
    zero_acc(acc);
    gemm_core(A, B, CH, m0, n0, sb, t, L, acc);
    epi_bias_f16(acc, L, m0, n0, CH, bias, true, Y);
}

// ============================================================================
// Merged K + V projection: grid (144,1,8); bx<72 -> K, else V.
// ============================================================================
__global__ __launch_bounds__(256, 1)
void proj_kv(const __half* __restrict__ tf,
             const __half* __restrict__ w_k, const __half* __restrict__ w_v,
             const float* __restrict__ b_k, const float* __restrict__ b_v,
             __half* __restrict__ kO, __half* __restrict__ vO)
{
    extern __shared__ char smem[];
    const uint32_t sb = smem_u32(smem);
    const int t = threadIdx.x;
    const int bz = blockIdx.z;
    const bool isV = blockIdx.x >= 72;
    const int bx = isV ? blockIdx.x - 72 : blockIdx.x;

    const __half* tfb = tf + S_NC * bz;
    const __half* A;
    const __half* B;
    const float* bias;
    __half* Y;
    int n0, m0, ldY;
    if (!isV) {
        n0 = (bx & 3) * 128;  m0 = (bx >> 2) * 128;
        A = tfb; B = w_k; bias = b_k; Y = kO + S_NC * bz; ldY = CH;
    } else {
        n0 = (bx % 18) * 128; m0 = (bx / 18) * 128;
        A = w_v; B = tfb; bias = b_v; Y = vO + S_NC * bz; ldY = NSP;
    }
    const LaneMap L = lane_map(t);

    float acc[2][8][4];
    zero_acc(acc);
    gemm_core(A, B, CH, m0, n0, sb, t, L, acc);
    epi_bias_f16(acc, L, m0, n0, ldY, bias, !isV, Y);
}

// ============================================================================
// S = scale * Q K^T (fp32 out). grid (18,18,8)
// ============================================================================
__global__ __launch_bounds__(256, 1)
void gemm_s(const __half* __restrict__ q, const __half* __restrict__ k,
            const float* __restrict__ scale, float* __restrict__ Sg)
{
    extern __shared__ char smem[];
    const uint32_t sb = smem_u32(smem);
    const int t = threadIdx.x;
    const int bz = blockIdx.z;
    const __half* A = q + S_NC * bz;
    const __half* B = k + S_NC * bz;
    float* Y = Sg + S_NN * bz;
    const int n0 = blockIdx.x * 128;
    const int m0 = blockIdx.y * 128;
    const LaneMap L = lane_map(t);

    float acc[2][8][4];
    zero_acc(acc);
    gemm_core(A, B, CH, m0, n0, sb, t, L, acc);

    const float sc = *scale;
#pragma unroll
    for (int mt = 0; mt < 2; mt++)
#pragma unroll
        for (int r2 = 0; r2 < 2; r2++) {
            const int m = m0 + L.wm + mt * 16 + L.grp + 8 * r2;
#pragma unroll
            for (int nt = 0; nt < 8; nt++) {
                const int n = n0 + L.wn + nt * 8 + L.qid * 2;
                *(float2*)&Y[(size_t)m * NSP + n] =
                    make_float2(acc[mt][nt][r2 * 2] * sc, acc[mt][nt][r2 * 2 + 1] * sc);
            }
        }
}

// ============================================================================
// out = V P^T + img (fp32 out). grid (18,4,8)
// ============================================================================
__global__ __launch_bounds__(256, 1)
void gemm_out(const __half* __restrict__ v, const __half* __restrict__ p,
              const float* __restrict__ img, float* __restrict__ out)
{
    extern __shared__ char smem[];
    const uint32_t sb = smem_u32(smem);
    const int t = threadIdx.x;
    const int bz = blockIdx.z;
    const __half* A = v + S_NC * bz;
    const __half* B = p + S_NN * bz;
    const float* res = img + S_NC * bz;
    float* Y = out + S_NC * bz;
    const int n0 = blockIdx.x * 128;
    const int m0 = blockIdx.y * 128;
    const LaneMap L = lane_map(t);

    float acc[2][8][4];
    zero_acc(acc);
    gemm_core(A, B, NSP, m0, n0, sb, t, L, acc);

#pragma unroll
    for (int mt = 0; mt < 2; mt++)
#pragma unroll
        for (int r2 = 0; r2 < 2; r2++) {
            const int m = m0 + L.wm + mt * 16 + L.grp + 8 * r2;
#pragma unroll
            for (int nt = 0; nt < 8; nt++) {
                const int n = n0 + L.wn + nt * 8 + L.qid * 2;
                const size_t off = (size_t)m * NSP + n;
                *(float2*)&Y[off] = make_float2(acc[mt][nt][r2 * 2] + res[off],
                                                acc[mt][nt][r2 * 2 + 1] + res[off + 1]);
            }
        }
}

// ---------------- merged pre-pass: transpose both text and img ----------------
__global__ void transpose2_f16(const float* __restrict__ text,
                               const float* __restrict__ img,
                               __half* __restrict__ tT, __half* __restrict__ iT)
{
    __shared__ float tile[32][33];
    const int z = blockIdx.z, op = z >> 3, bz = z & 7;
    const float* I = (op ? img : text) + (size_t)bz * CH * NSP;
    __half* H = (op ? iT : tT) + (size_t)bz * NSP * CH;
    const int n0 = blockIdx.x * 32, c0 = blockIdx.y * 32;
    const int tx = threadIdx.x, ty = threadIdx.y;
#pragma unroll
    for (int j = 0; j < 32; j += 8)
        tile[ty + j][tx] = I[(size_t)(c0 + ty + j) * NSP + n0 + tx];
    __syncthreads();
#pragma unroll
    for (int j = 0; j < 32; j += 8)
        H[(size_t)(n0 + ty + j) * CH + c0 + tx] = __float2half_rn(tile[tx][ty + j]);
}

__global__ void convert_w(const float* __restrict__ w0, const float* __restrict__ w1,
                          const float* __restrict__ w2, const float* __restrict__ w3,
                          __half* __restrict__ o)
{
    const int z = blockIdx.z;
    const float* w = (z == 0) ? w0 : (z == 1) ? w1 : (z == 2) ? w2 : w3;
    const int i = blockIdx.x * 256 + threadIdx.x;
    o[(size_t)z * CH * CH + i] = __float2half_rn(w[i]);
}

// ---------------- softmax over rows of S, emit f16 P -------------------------
__global__ void softmax_f16(const float* __restrict__ S, __half* __restrict__ Ph)
{
    __shared__ float red[256];
    const size_t ro = (size_t)blockIdx.x * NSP;
    const float* r = S + ro;
    const int t = threadIdx.x;

    float v[9];
    float mx = -1e30f;
#pragma unroll
    for (int i = 0; i < 9; i++) { v[i] = r[t + i * 256]; mx = fmaxf(mx, v[i]); }
    red[t] = mx;
    __syncthreads();
    for (int s = 128; s > 0; s >>= 1) {
        if (t < s) red[t] = fmaxf(red[t], red[t + s]);
        __syncthreads();
    }
    mx = red[0];
    __syncthreads();
    float sum = 0.f;
#pragma unroll
    for (int i = 0; i < 9; i++) { v[i] = __expf(v[i] - mx); sum += v[i]; }
    red[t] = sum;
    __syncthreads();
    for (int s = 128; s > 0; s >>= 1) {
        if (t < s) red[t] += red[t + s];
        __syncthreads();
    }
    const float inv = 1.0f / red[0];
#pragma unroll
    for (int i = 0; i < 9; i++)
        Ph[ro + t + i * 256] = __float2half_rn(v[i] * inv);
}

// ============================================================================
// Launch
// ============================================================================
extern "C" void kernel_launch(void* const* d_in, const int* in_sizes, int n_in,
                              void* d_out, int out_size)
{
    const float* img   = (const float*)d_in[0];
    const float* text  = (const float*)d_in[1];
    const float* w_tp  = (const float*)d_in[2];
    const float* b_tp  = (const float*)d_in[3];
    const float* w_q   = (const float*)d_in[4];
    const float* b_q   = (const float*)d_in[5];
    const float* w_k   = (const float*)d_in[6];
    const float* b_k   = (const float*)d_in[7];
    const float* w_v   = (const float*)d_in[8];
    const float* b_v   = (const float*)d_in[9];
    const float* scale = (const float*)d_in[10];

    __half *tT, *iT, *w, *tf, *q, *k, *v, *p;
    float* sp;
    cudaGetSymbolAddress((void**)&tT, g_tT);
    cudaGetSymbolAddress((void**)&iT, g_iT);
    cudaGetSymbolAddress((void**)&w,  g_w);
    cudaGetSymbolAddress((void**)&tf, g_tfT);
    cudaGetSymbolAddress((void**)&q,  g_qT);
    cudaGetSymbolAddress((void**)&k,  g_kT);
    cudaGetSymbolAddress((void**)&v,  g_v);
    cudaGetSymbolAddress((void**)&p,  g_P);
    cudaGetSymbolAddress((void**)&sp, g_S);

    cudaFuncSetAttribute((const void*)proj_tfq,
                         cudaFuncAttributeMaxDynamicSharedMemorySize, SMEM4_TOTAL);
    cudaFuncSetAttribute((const void*)proj_kv,
                         cudaFuncAttributeMaxDynamicSharedMemorySize, SMEM4_TOTAL);
    cudaFuncSetAttribute((const void*)gemm_s,
                         cudaFuncAttributeMaxDynamicSharedMemorySize, SMEM4_TOTAL);
    cudaFuncSetAttribute((const void*)gemm_out,
                         cudaFuncAttributeMaxDynamicSharedMemorySize, SMEM4_TOTAL);

    dim3 tb(32, 8);
    transpose2_f16<<<dim3(NSP / 32, CH / 32, 2 * BATCH), tb>>>(text, img, tT, iT);
    convert_w<<<dim3(CH * CH / 256, 1, 4), 256>>>(w_tp, w_q, w_k, w_v, w);

    dim3 blk(256);
    // tf + Q in one launch
    proj_tfq<<<dim3(CH / 128, NSP / 128, 2 * BATCH), blk, SMEM4_TOTAL>>>(
        tT, iT, w, b_tp, b_q, tf, q);
    // K + V in one launch
    proj_kv<<<dim3(144, 1, BATCH), blk, SMEM4_TOTAL>>>(
        tf, w + 2 * S_W, w + 3 * S_W, b_k, b_v, k, v);
    // S = scale * Q K^T
    gemm_s<<<dim3(NSP / 128, NSP / 128, BATCH), blk, SMEM4_TOTAL>>>(q, k, scale, sp);
    // P = softmax(S)
    softmax_f16<<<BATCH * NSP, 256>>>(sp, p);
    // out = V P^T + img
    gemm_out<<<dim3(NSP / 128, CH / 128, BATCH), blk, SMEM4_TOTAL>>>(
        v, p, img, (float*)d_out);
}

// round 17
// speedup vs baseline: 1.2490x; 1.2490x over previous
#include <cuda_runtime.h>
#include <cuda_fp16.h>
#include <cstdint>

#define NSP   2304
#define CH    512
#define BATCH 8

// ---- unified pure-f16 GEMM params (BK=64, 8 warps, warp tile 32x64) ----
#define BK2    64
#define PAD2   72                      // 64+8 halves; 144B stride, conflict-free
#define MAT2_B (128 * PAD2 * 2)        // 18432 bytes
#define STG2_B (2 * MAT2_B)            // A + B per stage = 36864
#define SMEM3_TOTAL (3 * STG2_B)       // 110592 bytes, 3-stage ring
#define S_NC  ((size_t)NSP * CH)
#define S_NN  ((size_t)NSP * NSP)
#define S_W   ((size_t)CH * CH)

// ---------------- scratch (device globals; no allocations) ------------------
__device__ __half g_tT  [(size_t)BATCH * NSP * CH];
__device__ __half g_iT  [(size_t)BATCH * NSP * CH];
__device__ __half g_w   [(size_t)4 * CH * CH];
__device__ __half g_tfT [(size_t)BATCH * NSP * CH];
__device__ __half g_qT  [(size_t)BATCH * NSP * CH];
__device__ __half g_kT  [(size_t)BATCH * NSP * CH];
__device__ __half g_v   [(size_t)BATCH * CH * NSP];
__device__ float  g_S   [(size_t)BATCH * NSP * NSP];
__device__ __half g_P   [(size_t)BATCH * NSP * NSP];

// ---------------- helpers ----------------------------------------------------
__device__ __forceinline__ uint32_t smem_u32(const void* p) {
    uint32_t a;
    asm("{ .reg .u64 t; cvta.to.shared.u64 t, %1; cvt.u32.u64 %0, t; }" : "=r"(a) : "l"(p));
    return a;
}
__device__ __forceinline__ void cp16(uint32_t saddr, const void* g) {
    asm volatile("cp.async.cg.shared.global [%0], [%1], 16;\n" :: "r"(saddr), "l"(g));
}
__device__ __forceinline__ void cp_commit() { asm volatile("cp.async.commit_group;\n"); }
template<int N> __device__ __forceinline__ void cp_wait() {
    asm volatile("cp.async.wait_group %0;\n" :: "n"(N));
}
__device__ __forceinline__ void ldsm4(unsigned (&r)[4], uint32_t addr) {
    asm volatile("ldmatrix.sync.aligned.m8n8.x4.shared.b16 {%0,%1,%2,%3}, [%4];"
        : "=r"(r[0]), "=r"(r[1]), "=r"(r[2]), "=r"(r[3]) : "r"(addr));
}
__device__ __forceinline__ void mma16816(float (&d)[4], const unsigned (&a)[4],
                                         unsigned b0, unsigned b1) {
    asm volatile(
        "mma.sync.aligned.m16n8k16.row.col.f32.f16.f16.f32 "
        "{%0,%1,%2,%3}, {%4,%5,%6,%7}, {%8,%9}, {%0,%1,%2,%3};\n"
        : "+f"(d[0]), "+f"(d[1]), "+f"(d[2]), "+f"(d[3])
        : "r"(a[0]), "r"(a[1]), "r"(a[2]), "r"(a[3]), "r"(b0), "r"(b1));
}

// ---------------- lane mapping (8 warps, warp tile 32x64) ---------------------
struct LaneMap {
    int lane, warp, wm, wn, grp, qid;
    uint32_t offA, offB;
};
__device__ __forceinline__ LaneMap lane_map(int t) {
    LaneMap L;
    L.lane = t & 31;
    L.warp = t >> 5;
    L.wm   = (L.warp & 3) * 32;
    L.wn   = (L.warp >> 2) * 64;
    L.grp  = L.lane >> 2;
    L.qid  = L.lane & 3;
    L.offA = (uint32_t)(L.wm + (L.lane & 15)) * (PAD2 * 2) + (L.lane >> 4) * 16;
    L.offB = (uint32_t)(L.wn + ((L.lane >> 4) & 1) * 8 + (L.lane & 7)) * (PAD2 * 2)
           + ((L.lane >> 3) & 1) * 16;
    return L;
}

// ============================================================================
// GEMM core: CTA 128x128, 256 threads, BK=64, 3-stage cp.async ring, ONE
// __syncthreads per chunk (R15), PLUS register double-buffered fragments:
// b prefetched 1 step ahead, a prefetched 4 steps ahead -> LDSM->HMMA RAW
// distance >= 4 mma groups. MMA/accumulation order identical to R15.
// ============================================================================
__device__ __forceinline__ void gemm_core(
    const __half* __restrict__ A, const __half* __restrict__ B,
    int K, int m0, int n0, uint32_t sb, int t,
    const LaneMap& L, float (&acc)[2][8][4])
{
    auto load_chunk = [&](int c) {
        const int k0 = c * BK2;
        const uint32_t so = sb + (c % 3) * STG2_B;
#pragma unroll
        for (int i = 0; i < 4; i++) {
            const int idx = t + 256 * i;
            const int kg = idx & 7, r = idx >> 3;
            cp16(so + r * (PAD2 * 2) + kg * 16,
                 &A[(size_t)(m0 + r) * K + k0 + kg * 8]);
        }
#pragma unroll
        for (int i = 0; i < 4; i++) {
            const int idx = t + 256 * i;
            const int kg = idx & 7, r = idx >> 3;
            cp16(so + MAT2_B + r * (PAD2 * 2) + kg * 16,
                 &B[(size_t)(n0 + r) * K + k0 + kg * 8]);
        }
        cp_commit();
    };

    const int nch = K / BK2;
    load_chunk(0);
    if (nch > 1) load_chunk(1);

    for (int c = 0; c < nch; c++) {
        if (c + 1 < nch) cp_wait<1>(); else cp_wait<0>();
        __syncthreads();                 // single barrier per chunk (R15)

        const uint32_t stg = sb + (c % 3) * STG2_B;

        // fragment double buffers
        unsigned abuf[2][2][4];          // [ks parity][mt][frag]
        unsigned bbuf[2][4];             // [step parity][frag]

        // preload ks=0 A and (ks=0,np=0) B
        ldsm4(abuf[0][0], stg + L.offA);
        ldsm4(abuf[0][1], stg + L.offA + 16 * (PAD2 * 2));
        ldsm4(bbuf[0],    stg + MAT2_B + L.offB);

#pragma unroll
        for (int i = 0; i < 16; i++) {
            const int ks = i >> 2, np = i & 3;
            // prefetch B for step i+1
            if (i + 1 < 16) {
                const int ks1 = (i + 1) >> 2, np1 = (i + 1) & 3;
                ldsm4(bbuf[(i + 1) & 1],
                      stg + MAT2_B + L.offB + np1 * 16 * (PAD2 * 2) + ks1 * 32);
            }
            // prefetch A for ks+1 (4-step lead)
            if (np == 0 && ks < 3) {
                ldsm4(abuf[(ks + 1) & 1][0],
                      stg + L.offA + (ks + 1) * 32);
                ldsm4(abuf[(ks + 1) & 1][1],
                      stg + L.offA + 16 * (PAD2 * 2) + (ks + 1) * 32);
            }
            const unsigned (&a0)[4] = abuf[ks & 1][0];
            const unsigned (&a1)[4] = abuf[ks & 1][1];
            const unsigned (&b)[4]  = bbuf[i & 1];
            mma16816(acc[0][2 * np],     a0, b[0], b[1]);
            mma16816(acc[0][2 * np + 1], a0, b[2], b[3]);
            mma16816(acc[1][2 * np],     a1, b[0], b[1]);
            mma16816(acc[1][2 * np + 1], a1, b[2], b[3]);
        }
        // no trailing barrier: load(c+2) targets stage (c+2)%3 == (c-1)%3,
        // drained before this iteration's barrier.
        if (c + 2 < nch) load_chunk(c + 2);
    }
}

__device__ __forceinline__ void zero_acc(float (&acc)[2][8][4]) {
#pragma unroll
    for (int mt = 0; mt < 2; mt++)
#pragma unroll
        for (int nt = 0; nt < 8; nt++)
#pragma unroll
            for (int r = 0; r < 4; r++) acc[mt][nt][r] = 0.f;
}

// ---------------- f16 epilogue with bias (biasN: bias[n] else bias[m]) --------
__device__ __forceinline__ void epi_bias_f16(
    float (&acc)[2][8][4], const LaneMap& L, int m0, int n0, int ldY,
    const float* __restrict__ bias, bool biasN, __half* __restrict__ Y)
{
#pragma unroll
    for (int mt = 0; mt < 2; mt++)
#pragma unroll
        for (int r2 = 0; r2 < 2; r2++) {
            const int m = m0 + L.wm + mt * 16 + L.grp + 8 * r2;
            const float bvr = biasN ? 0.f : bias[m];
#pragma unroll
            for (int nt = 0; nt < 8; nt++) {
                const int n = n0 + L.wn + nt * 8 + L.qid * 2;
                float v0 = acc[mt][nt][r2 * 2 + 0];
                float v1 = acc[mt][nt][r2 * 2 + 1];
                if (biasN) { v0 += bias[n]; v1 += bias[n + 1]; }
                else       { v0 += bvr;     v1 += bvr; }
                *(__half2*)&Y[(size_t)m * ldY + n] =
                    __halves2half2(__float2half_rn(v0), __float2half_rn(v1));
            }
        }
}

// ============================================================================
// Merged tf + Q projection: z = 0..15, op = z>>3 (0: tf, 1: Q). grid (4,18,16)
// ============================================================================
__global__ __launch_bounds__(256, 2)
void proj_tfq(const __half* __restrict__ tT, const __half* __restrict__ iT,
              const __half* __restrict__ w,
              const float* __restrict__ b_tp, const float* __restrict__ b_q,
              __half* __restrict__ tf, __half* __restrict__ q)
{
    extern __shared__ char smem[];
    const uint32_t sb = smem_u32(smem);
    const int t = threadIdx.x;
    const int z = blockIdx.z, op = z >> 3, bz = z & 7;

    const __half* A = (op ? iT : tT) + S_NC * bz;
    const __half* B = w + (size_t)op * S_W;
    const float* bias = op ? b_q : b_tp;
    __half* Y = (op ? q : tf) + S_NC * bz;

    const int n0 = blockIdx.x * 128;
    const int m0 = blockIdx.y * 128;
    const LaneMap L = lane_map(t);

    float acc[2][8][4];
    zero_acc(acc);
    gemm_core(A, B, CH, m0, n0, sb, t, L, acc);
    epi_bias_f16(acc, L, m0, n0, CH, bias, true, Y);
}

// ============================================================================
// Merged K + V projection: grid (144,1,8); bx<72 -> K, else V.
// ============================================================================
__global__ __launch_bounds__(256, 2)
void proj_kv(const __half* __restrict__ tf,
             const __half* __restrict__ w_k, const __half* __restrict__ w_v,
             const float* __restrict__ b_k, const float* __restrict__ b_v,
             __half* __restrict__ kO, __half* __restrict__ vO)
{
    extern __shared__ char smem[];
    const uint32_t sb = smem_u32(smem);
    const int t = threadIdx.x;
    const int bz = blockIdx.z;
    const bool isV = blockIdx.x >= 72;
    const int bx = isV ? blockIdx.x - 72 : blockIdx.x;

    const __half* tfb = tf + S_NC * bz;
    const __half* A;
    const __half* B;
    const float* bias;
    __half* Y;
    int n0, m0, ldY;
    if (!isV) {
        n0 = (bx & 3) * 128;  m0 = (bx >> 2) * 128;
        A = tfb; B = w_k; bias = b_k; Y = kO + S_NC * bz; ldY = CH;
    } else {
        n0 = (bx % 18) * 128; m0 = (bx / 18) * 128;
        A = w_v; B = tfb; bias = b_v; Y = vO + S_NC * bz; ldY = NSP;
    }
    const LaneMap L = lane_map(t);

    float acc[2][8][4];
    zero_acc(acc);
    gemm_core(A, B, CH, m0, n0, sb, t, L, acc);
    epi_bias_f16(acc, L, m0, n0, ldY, bias, !isV, Y);
}

// ============================================================================
// S = scale * Q K^T (fp32 out). grid (18,18,8)
// ============================================================================
__global__ __launch_bounds__(256, 2)
void gemm_s(const __half* __restrict__ q, const __half* __restrict__ k,
            const float* __restrict__ scale, float* __restrict__ Sg)
{
    extern __shared__ char smem[];
    const uint32_t sb = smem_u32(smem);
    const int t = threadIdx.x;
    const int bz = blockIdx.z;
    const __half* A = q + S_NC * bz;
    const __half* B = k + S_NC * bz;
    float* Y = Sg + S_NN * bz;
    const int n0 = blockIdx.x * 128;
    const int m0 = blockIdx.y * 128;
    const LaneMap L = lane_map(t);

    float acc[2][8][4];
    zero_acc(acc);
    gemm_core(A, B, CH, m0, n0, sb, t, L, acc);

    const float sc = *scale;
#pragma unroll
    for (int mt = 0; mt < 2; mt++)
#pragma unroll
        for (int r2 = 0; r2 < 2; r2++) {
            const int m = m0 + L.wm + mt * 16 + L.grp + 8 * r2;
#pragma unroll
            for (int nt = 0; nt < 8; nt++) {
                const int n = n0 + L.wn + nt * 8 + L.qid * 2;
                *(float2*)&Y[(size_t)m * NSP + n] =
                    make_float2(acc[mt][nt][r2 * 2] * sc, acc[mt][nt][r2 * 2 + 1] * sc);
            }
        }
}

// ============================================================================
// out = V P^T + img (fp32 out). grid (18,4,8)
// ============================================================================
__global__ __launch_bounds__(256, 2)
void gemm_out(const __half* __restrict__ v, const __half* __restrict__ p,
              const float* __restrict__ img, float* __restrict__ out)
{
    extern __shared__ char smem[];
    const uint32_t sb = smem_u32(smem);
    const int t = threadIdx.x;
    const int bz = blockIdx.z;
    const __half* A = v + S_NC * bz;
    const __half* B = p + S_NN * bz;
    const float* res = img + S_NC * bz;
    float* Y = out + S_NC * bz;
    const int n0 = blockIdx.x * 128;
    const int m0 = blockIdx.y * 128;
    const LaneMap L = lane_map(t);

    float acc[2][8][4];
    zero_acc(acc);
    gemm_core(A, B, NSP, m0, n0, sb, t, L, acc);

#pragma unroll
    for (int mt = 0; mt < 2; mt++)
#pragma unroll
        for (int r2 = 0; r2 < 2; r2++) {
            const int m = m0 + L.wm + mt * 16 + L.grp + 8 * r2;
#pragma unroll
            for (int nt = 0; nt < 8; nt++) {
                const int n = n0 + L.wn + nt * 8 + L.qid * 2;
                const size_t off = (size_t)m * NSP + n;
                *(float2*)&Y[off] = make_float2(acc[mt][nt][r2 * 2] + res[off],
                                                acc[mt][nt][r2 * 2 + 1] + res[off + 1]);
            }
        }
}

// ---------------- merged pre-pass: transpose both text and img ----------------
__global__ void transpose2_f16(const float* __restrict__ text,
                               const float* __restrict__ img,
                               __half* __restrict__ tT, __half* __restrict__ iT)
{
    __shared__ float tile[32][33];
    const int z = blockIdx.z, op = z >> 3, bz = z & 7;
    const float* I = (op ? img : text) + (size_t)bz * CH * NSP;
    __half* H = (op ? iT : tT) + (size_t)bz * NSP * CH;
    const int n0 = blockIdx.x * 32, c0 = blockIdx.y * 32;
    const int tx = threadIdx.x, ty = threadIdx.y;
#pragma unroll
    for (int j = 0; j < 32; j += 8)
        tile[ty + j][tx] = I[(size_t)(c0 + ty + j) * NSP + n0 + tx];
    __syncthreads();
#pragma unroll
    for (int j = 0; j < 32; j += 8)
        H[(size_t)(n0 + ty + j) * CH + c0 + tx] = __float2half_rn(tile[tx][ty + j]);
}

__global__ void convert_w(const float* __restrict__ w0, const float* __restrict__ w1,
                          const float* __restrict__ w2, const float* __restrict__ w3,
                          __half* __restrict__ o)
{
    const int z = blockIdx.z;
    const float* w = (z == 0) ? w0 : (z == 1) ? w1 : (z == 2) ? w2 : w3;
    const int i = blockIdx.x * 256 + threadIdx.x;
    o[(size_t)z * CH * CH + i] = __float2half_rn(w[i]);
}

// ---------------- softmax over rows of S, emit f16 P -------------------------
__global__ void softmax_f16(const float* __restrict__ S, __half* __restrict__ Ph)
{
    __shared__ float red[256];
    const size_t ro = (size_t)blockIdx.x * NSP;
    const float* r = S + ro;
    const int t = threadIdx.x;

    float v[9];
    float mx = -1e30f;
#pragma unroll
    for (int i = 0; i < 9; i++) { v[i] = r[t + i * 256]; mx = fmaxf(mx, v[i]); }
    red[t] = mx;
    __syncthreads();
    for (int s = 128; s > 0; s >>= 1) {
        if (t < s) red[t] = fmaxf(red[t], red[t + s]);
        __syncthreads();
    }
    mx = red[0];
    __syncthreads();
    float sum = 0.f;
#pragma unroll
    for (int i = 0; i < 9; i++) { v[i] = __expf(v[i] - mx); sum += v[i]; }
    red[t] = sum;
    __syncthreads();
    for (int s = 128; s > 0; s >>= 1) {
        if (t < s) red[t] += red[t + s];
        __syncthreads();
    }
    const float inv = 1.0f / red[0];
#pragma unroll
    for (int i = 0; i < 9; i++)
        Ph[ro + t + i * 256] = __float2half_rn(v[i] * inv);
}

// ============================================================================
// Launch
// ============================================================================
extern "C" void kernel_launch(void* const* d_in, const int* in_sizes, int n_in,
                              void* d_out, int out_size)
{
    const float* img   = (const float*)d_in[0];
    const float* text  = (const float*)d_in[1];
    const float* w_tp  = (const float*)d_in[2];
    const float* b_tp  = (const float*)d_in[3];
    const float* w_q   = (const float*)d_in[4];
    const float* b_q   = (const float*)d_in[5];
    const float* w_k   = (const float*)d_in[6];
    const float* b_k   = (const float*)d_in[7];
    const float* w_v   = (const float*)d_in[8];
    const float* b_v   = (const float*)d_in[9];
    const float* scale = (const float*)d_in[10];

    __half *tT, *iT, *w, *tf, *q, *k, *v, *p;
    float* sp;
    cudaGetSymbolAddress((void**)&tT, g_tT);
    cudaGetSymbolAddress((void**)&iT, g_iT);
    cudaGetSymbolAddress((void**)&w,  g_w);
    cudaGetSymbolAddress((void**)&tf, g_tfT);
    cudaGetSymbolAddress((void**)&q,  g_qT);
    cudaGetSymbolAddress((void**)&k,  g_kT);
    cudaGetSymbolAddress((void**)&v,  g_v);
    cudaGetSymbolAddress((void**)&p,  g_P);
    cudaGetSymbolAddress((void**)&sp, g_S);

    cudaFuncSetAttribute((const void*)proj_tfq,
                         cudaFuncAttributeMaxDynamicSharedMemorySize, SMEM3_TOTAL);
    cudaFuncSetAttribute((const void*)proj_kv,
                         cudaFuncAttributeMaxDynamicSharedMemorySize, SMEM3_TOTAL);
    cudaFuncSetAttribute((const void*)gemm_s,
                         cudaFuncAttributeMaxDynamicSharedMemorySize, SMEM3_TOTAL);
    cudaFuncSetAttribute((const void*)gemm_out,
                         cudaFuncAttributeMaxDynamicSharedMemorySize, SMEM3_TOTAL);

    dim3 tb(32, 8);
    transpose2_f16<<<dim3(NSP / 32, CH / 32, 2 * BATCH), tb>>>(text, img, tT, iT);
    convert_w<<<dim3(CH * CH / 256, 1, 4), 256>>>(w_tp, w_q, w_k, w_v, w);

    dim3 blk(256);
    // tf + Q in one launch
    proj_tfq<<<dim3(CH / 128, NSP / 128, 2 * BATCH), blk, SMEM3_TOTAL>>>(
        tT, iT, w, b_tp, b_q, tf, q);
    // K + V in one launch
    proj_kv<<<dim3(144, 1, BATCH), blk, SMEM3_TOTAL>>>(
        tf, w + 2 * S_W, w + 3 * S_W, b_k, b_v, k, v);
    // S = scale * Q K^T
    gemm_s<<<dim3(NSP / 128, NSP / 128, BATCH), blk, SMEM3_TOTAL>>>(q, k, scale, sp);
    // P = softmax(S)
    softmax_f16<<<BATCH * NSP, 256>>>(sp, p);
    // out = V P^T + img
    gemm_out<<<dim3(NSP / 128, CH / 128, BATCH), blk, SMEM3_TOTAL>>>(
        v, p, img, (float*)d_out);
}